// round 6
// baseline (speedup 1.0000x reference)
#include <cuda_runtime.h>

#define BB 4
#define NN 8192
#define THREADS 256
#define UQ 4            // queries per thread
#define QBLOCKS 8       // 8 * 256 * 4 = 8192 query coverage
#define MSLICES 4
#define CHUNK 1024      // float4 db entries staged in smem (16KB)
#define FBLOCKS 64      // finalize blocks

// Scratch (device globals: no allocations allowed)
__device__ float4 g_q [2][BB][NN];  // [0]=clean query (c, |c|^2), [1]=pred query (p, |p|^2)
__device__ float4 g_db[2][BB][NN];  // [0]=pred db (-2p, |p|^2),   [1]=clean db (-2c, |c|^2)
__device__ float  g_minbuf[2][BB][NN];
__device__ int    g_nv[BB];
__device__ float  g_l1sum;
__device__ float  g_cd;
__device__ int    g_ticket;

__device__ __forceinline__ void atomicMinFloat(float* addr, float value) {
    if (value >= 0.0f)
        atomicMin((int*)addr, __float_as_int(value));
    else
        atomicMax((unsigned int*)addr, __float_as_uint(value));
}

__global__ void init_kernel() {
    int idx = blockIdx.x * blockDim.x + threadIdx.x;
    if (idx < 2 * BB * NN)
        ((float*)g_minbuf)[idx] = __int_as_float(0x7F800000);  // +inf
    if (idx < BB) g_nv[idx] = 0;
    if (idx == 0) { g_l1sum = 0.0f; g_cd = 0.0f; g_ticket = 0; }
}

__global__ void prep_kernel(const float* __restrict__ pred,
                            const float* __restrict__ target,
                            const int*   __restrict__ mask,
                            const float* __restrict__ points) {
    int gid = blockIdx.x * blockDim.x + threadIdx.x;   // grid exactly covers BB*NN
    int b = gid / NN;
    int base = gid * 3;
    float p0 = pred[base], p1 = pred[base + 1], p2 = pred[base + 2];
    float t0 = target[base], t1 = target[base + 1], t2 = target[base + 2];
    int m = mask[gid];
    float li = 0.0f;
    if (m) {
        li = (fabsf(p0 - t0) + fabsf(p1 - t1) + fabsf(p2 - t2)) * (1.0f / 3.0f);
        float x0 = points[base], x1 = points[base + 1], x2 = points[base + 2];
        float c0 = x0 + t0, c1 = x1 + t1, c2 = x2 + t2;     // clean
        float q0 = x0 + p0, q1 = x1 + p1, q2 = x2 + p2;     // predp
        float cn = fmaf(c0, c0, fmaf(c1, c1, c2 * c2));
        float pn = fmaf(q0, q0, fmaf(q1, q1, q2 * q2));
        int slot = atomicAdd(&g_nv[b], 1);
        g_q [0][b][slot] = make_float4(c0, c1, c2, cn);
        g_q [1][b][slot] = make_float4(q0, q1, q2, pn);
        g_db[0][b][slot] = make_float4(-2.0f * q0, -2.0f * q1, -2.0f * q2, pn);
        g_db[1][b][slot] = make_float4(-2.0f * c0, -2.0f * c1, -2.0f * c2, cn);
    }
    // warp-reduce l1 partial, one atomic per warp
    #pragma unroll
    for (int o = 16; o; o >>= 1) li += __shfl_down_sync(0xFFFFFFFFu, li, o);
    if ((threadIdx.x & 31) == 0) atomicAdd(&g_l1sum, li);
}

__global__ void __launch_bounds__(THREADS)
pair_kernel() {
    int z = blockIdx.z;
    int dir = z & 1;
    int b = z >> 1;
    int nv = g_nv[b];
    int qbase = blockIdx.x * (THREADS * UQ);
    if (qbase >= nv) return;                          // block-uniform
    int len = (nv + MSLICES - 1) / MSLICES;
    int m0 = blockIdx.y * len;
    int m1 = min(m0 + len, nv);
    if (m0 >= m1) return;                             // block-uniform

    __shared__ float4 sdb[CHUNK];

    const float4* __restrict__ Q  = g_q[dir][b];
    const float4* __restrict__ DB = g_db[dir][b];

    float qx[UQ], qy[UQ], qz[UQ], mn[UQ];
    #pragma unroll
    for (int u = 0; u < UQ; u++) {
        int qi = qbase + u * THREADS + threadIdx.x;
        float4 q = (qi < nv) ? Q[qi] : make_float4(0.f, 0.f, 0.f, 0.f);
        qx[u] = q.x; qy[u] = q.y; qz[u] = q.z;
        mn[u] = 3.4e38f;
    }

    for (int mc = m0; mc < m1; mc += CHUNK) {
        int cnt = min(CHUNK, m1 - mc);
        __syncthreads();
        for (int t = threadIdx.x; t < cnt; t += THREADS) sdb[t] = DB[mc + t];
        __syncthreads();
        #pragma unroll 4
        for (int j = 0; j < cnt; j++) {
            float4 p = sdb[j];                        // broadcast, conflict-free
            #pragma unroll
            for (int u = 0; u < UQ; u++) {
                // e = |p|^2 - 2*dot(p, q)   (query norm folded in at finalize)
                float e = fmaf(p.x, qx[u], fmaf(p.y, qy[u], fmaf(p.z, qz[u], p.w)));
                mn[u] = fminf(mn[u], e);
            }
        }
    }

    #pragma unroll
    for (int u = 0; u < UQ; u++) {
        int qi = qbase + u * THREADS + threadIdx.x;
        if (qi < nv) atomicMinFloat(&g_minbuf[dir][b][qi], mn[u]);
    }
}

__global__ void __launch_bounds__(256)
finalize_kernel(float* __restrict__ out) {
    __shared__ float red[256];
    const int total = 2 * BB * NN;
    float acc = 0.0f;
    // cache per-batch reciprocals
    float inv_nv[BB];
    #pragma unroll
    for (int b = 0; b < BB; b++) {
        int nv = g_nv[b];
        inv_nv[b] = (nv > 0) ? (1.0f / (float)nv) : 0.0f;
    }
    for (int idx = blockIdx.x * 256 + threadIdx.x; idx < total; idx += FBLOCKS * 256) {
        int dir = idx / (BB * NN);
        int r = idx % (BB * NN);
        int b = r / NN;
        int i = r % NN;
        if (i < g_nv[b]) {
            float e  = g_minbuf[dir][b][i];
            float qw = g_q[dir][b][i].w;
            float v  = fmaxf(qw + e, 0.0f);           // d2 clamp, monotone-commuted past the min
            acc = fmaf(v, inv_nv[b], acc);
        }
    }
    // block reduction
    red[threadIdx.x] = acc;
    __syncthreads();
    #pragma unroll
    for (int s = 128; s > 0; s >>= 1) {
        if (threadIdx.x < s) red[threadIdx.x] += red[threadIdx.x + s];
        __syncthreads();
    }
    if (threadIdx.x == 0) {
        atomicAdd(&g_cd, red[0]);
        __threadfence();
        int ticket = atomicAdd(&g_ticket, 1);
        if (ticket == FBLOCKS - 1) {
            int cnt = g_nv[0] + g_nv[1] + g_nv[2] + g_nv[3];
            float l1 = g_l1sum / (float)max(cnt, 1);
            float cd = g_cd / (float)BB;
            out[0] = 0.5f * (l1 + cd);
        }
    }
}

extern "C" void kernel_launch(void* const* d_in, const int* in_sizes, int n_in,
                              void* d_out, int out_size) {
    const float* pred   = (const float*)d_in[0];
    const float* target = (const float*)d_in[1];
    const int*   mask   = (const int*)d_in[2];
    const float* points = (const float*)d_in[3];

    init_kernel<<<(2 * BB * NN + 255) / 256, 256>>>();
    prep_kernel<<<(BB * NN) / 256, 256>>>(pred, target, mask, points);
    pair_kernel<<<dim3(QBLOCKS, MSLICES, 2 * BB), THREADS>>>();
    finalize_kernel<<<FBLOCKS, 256>>>((float*)d_out);
}

// round 7
// speedup vs baseline: 1.4192x; 1.4192x over previous
#include <cuda_runtime.h>

#define BB 4
#define NN 8192
#define PAIRS (NN / 2)
#define THREADS 256
#define UQ 4            // queries per thread
#define QBLOCKS 8       // worst-case coverage 8*1024 = 8192 queries
#define MSLICES 16
#define CHUNKP 512      // db pairs staged in smem (16KB)
#define FBLOCKS 256

// Scratch (device globals: no allocations allowed)
__device__ float4 g_q [2][BB][NN];         // query points (x,y,z,|.|^2)
__device__ float  g_qw[2][BB][NN];         // contiguous copy of query norms (finalize)
__device__ float  g_db2[2][BB][PAIRS][8];  // pair-interleaved db: [x0x1][y0y1][z0z1][w0w1]
__device__ float  g_minbuf[2][BB][NN];
__device__ int    g_nv[BB];
__device__ float  g_l1sum;
__device__ float  g_cd;
__device__ int    g_ticket;

__device__ __forceinline__ void atomicMinFloat(float* addr, float value) {
    if (value >= 0.0f)
        atomicMin((int*)addr, __float_as_int(value));
    else
        atomicMax((unsigned int*)addr, __float_as_uint(value));
}

__device__ __forceinline__ unsigned long long pack2(float v) {
    unsigned long long r;
    asm("mov.b64 %0, {%1, %1};" : "=l"(r) : "f"(v));
    return r;
}

__device__ __forceinline__ unsigned long long fma2(unsigned long long a,
                                                   unsigned long long b,
                                                   unsigned long long c) {
    unsigned long long d;
    asm("fma.rn.f32x2 %0, %1, %2, %3;" : "=l"(d) : "l"(a), "l"(b), "l"(c));
    return d;
}

__global__ void init_kernel() {
    int idx = blockIdx.x * blockDim.x + threadIdx.x;
    if (idx < 2 * BB * NN) {
        ((float*)g_minbuf)[idx] = __int_as_float(0x7F800000);  // +inf
        // sentinel norm for unwritten/pad db halves: huge -> never wins the min
        int gpair = idx >> 1;
        int h = idx & 1;
        ((float*)g_db2)[gpair * 8 + 6 + h] = 1e30f;
    }
    if (idx < BB) g_nv[idx] = 0;
    if (idx == 0) { g_l1sum = 0.0f; g_cd = 0.0f; g_ticket = 0; }
}

__global__ void prep_kernel(const float* __restrict__ pred,
                            const float* __restrict__ target,
                            const int*   __restrict__ mask,
                            const float* __restrict__ points) {
    int gid = blockIdx.x * blockDim.x + threadIdx.x;   // grid exactly covers BB*NN
    int b = gid / NN;
    int base = gid * 3;
    float p0 = pred[base], p1 = pred[base + 1], p2 = pred[base + 2];
    float t0 = target[base], t1 = target[base + 1], t2 = target[base + 2];
    int m = mask[gid];
    float li = 0.0f;
    if (m) {
        li = (fabsf(p0 - t0) + fabsf(p1 - t1) + fabsf(p2 - t2)) * (1.0f / 3.0f);
        float x0 = points[base], x1 = points[base + 1], x2 = points[base + 2];
        float c0 = x0 + t0, c1 = x1 + t1, c2 = x2 + t2;     // clean
        float q0 = x0 + p0, q1 = x1 + p1, q2 = x2 + p2;     // predp
        float cn = fmaf(c0, c0, fmaf(c1, c1, c2 * c2));
        float pn = fmaf(q0, q0, fmaf(q1, q1, q2 * q2));
        int slot = atomicAdd(&g_nv[b], 1);
        g_q [0][b][slot] = make_float4(c0, c1, c2, cn);
        g_q [1][b][slot] = make_float4(q0, q1, q2, pn);
        g_qw[0][b][slot] = cn;
        g_qw[1][b][slot] = pn;
        int pi = slot >> 1, h = slot & 1;
        // dir 0: queries=clean, db=pred points (store -2*p, |p|^2)
        float* d0 = &g_db2[0][b][pi][0];
        d0[0 + h] = -2.0f * q0; d0[2 + h] = -2.0f * q1;
        d0[4 + h] = -2.0f * q2; d0[6 + h] = pn;
        // dir 1: queries=pred, db=clean points
        float* d1 = &g_db2[1][b][pi][0];
        d1[0 + h] = -2.0f * c0; d1[2 + h] = -2.0f * c1;
        d1[4 + h] = -2.0f * c2; d1[6 + h] = cn;
    }
    #pragma unroll
    for (int o = 16; o; o >>= 1) li += __shfl_down_sync(0xFFFFFFFFu, li, o);
    if ((threadIdx.x & 31) == 0) atomicAdd(&g_l1sum, li);
}

__global__ void __launch_bounds__(THREADS)
pair_kernel() {
    int z = blockIdx.z;
    int dir = z & 1;
    int b = z >> 1;
    int nv = g_nv[b];
    int qbase = blockIdx.x * (THREADS * UQ);
    if (qbase >= nv) return;                          // block-uniform
    int nvp = (nv + 1) >> 1;                          // padded pair count
    int len = (nvp + MSLICES - 1) / MSLICES;
    int m0 = blockIdx.y * len;
    int m1 = min(m0 + len, nvp);
    if (m0 >= m1) return;                             // block-uniform

    __shared__ float4 sdb[2 * CHUNKP];

    const float4* __restrict__ Q  = g_q[dir][b];
    const float4* __restrict__ DB = (const float4*)&g_db2[dir][b][0][0];

    unsigned long long qx2[UQ], qy2[UQ], qz2[UQ];
    float mnl[UQ], mnh[UQ];
    #pragma unroll
    for (int u = 0; u < UQ; u++) {
        int qi = min(qbase + u * THREADS + (int)threadIdx.x, nv - 1);
        float4 q = Q[qi];
        qx2[u] = pack2(q.x); qy2[u] = pack2(q.y); qz2[u] = pack2(q.z);
        mnl[u] = 3.4e38f; mnh[u] = 3.4e38f;
    }

    for (int mc = m0; mc < m1; mc += CHUNKP) {
        int cnt = min(CHUNKP, m1 - mc);
        __syncthreads();
        for (int t = threadIdx.x; t < cnt * 2; t += THREADS) sdb[t] = DB[2 * mc + t];
        __syncthreads();
        #pragma unroll 2
        for (int j = 0; j < cnt; j++) {
            ulonglong2 xy = *(const ulonglong2*)(sdb + 2 * j);      // x0x1 | y0y1
            ulonglong2 zw = *(const ulonglong2*)(sdb + 2 * j + 1);  // z0z1 | w0w1
            #pragma unroll
            for (int u = 0; u < UQ; u++) {
                // e2 = {w + (-2p).q} for both db halves at once
                unsigned long long acc = fma2(zw.x, qz2[u], zw.y);
                acc = fma2(xy.y, qy2[u], acc);
                acc = fma2(xy.x, qx2[u], acc);
                float elo, ehi;
                asm("mov.b64 {%0, %1}, %2;" : "=f"(elo), "=f"(ehi) : "l"(acc));
                mnl[u] = fminf(mnl[u], elo);
                mnh[u] = fminf(mnh[u], ehi);
            }
        }
    }

    #pragma unroll
    for (int u = 0; u < UQ; u++) {
        int qi = qbase + u * THREADS + (int)threadIdx.x;
        if (qi < nv) atomicMinFloat(&g_minbuf[dir][b][qi], fminf(mnl[u], mnh[u]));
    }
}

__global__ void __launch_bounds__(256)
finalize_kernel(float* __restrict__ out) {
    __shared__ float red[256];
    const int total = 2 * BB * NN;
    float acc = 0.0f;
    float inv_nv[BB];
    #pragma unroll
    for (int b = 0; b < BB; b++) {
        int nv = g_nv[b];
        inv_nv[b] = (nv > 0) ? (1.0f / (float)nv) : 0.0f;
    }
    for (int idx = blockIdx.x * 256 + threadIdx.x; idx < total; idx += FBLOCKS * 256) {
        int b = (idx >> 13) & (BB - 1);
        int i = idx & (NN - 1);
        if (i < g_nv[b]) {
            float e  = ((const float*)g_minbuf)[idx];
            float qw = ((const float*)g_qw)[idx];
            float v  = fmaxf(qw + e, 0.0f);           // d2 clamp, monotone-commuted past the min
            acc = fmaf(v, inv_nv[b], acc);
        }
    }
    red[threadIdx.x] = acc;
    __syncthreads();
    #pragma unroll
    for (int s = 128; s > 0; s >>= 1) {
        if (threadIdx.x < s) red[threadIdx.x] += red[threadIdx.x + s];
        __syncthreads();
    }
    if (threadIdx.x == 0) {
        atomicAdd(&g_cd, red[0]);
        __threadfence();
        int ticket = atomicAdd(&g_ticket, 1);
        if (ticket == FBLOCKS - 1) {
            int cnt = g_nv[0] + g_nv[1] + g_nv[2] + g_nv[3];
            float l1 = g_l1sum / (float)max(cnt, 1);
            float cd = g_cd / (float)BB;
            out[0] = 0.5f * (l1 + cd);
        }
    }
}

extern "C" void kernel_launch(void* const* d_in, const int* in_sizes, int n_in,
                              void* d_out, int out_size) {
    const float* pred   = (const float*)d_in[0];
    const float* target = (const float*)d_in[1];
    const int*   mask   = (const int*)d_in[2];
    const float* points = (const float*)d_in[3];

    init_kernel<<<(2 * BB * NN + 255) / 256, 256>>>();
    prep_kernel<<<(BB * NN) / 256, 256>>>(pred, target, mask, points);
    pair_kernel<<<dim3(QBLOCKS, MSLICES, 2 * BB), THREADS>>>();
    finalize_kernel<<<FBLOCKS, 256>>>((float*)d_out);
}

// round 8
// speedup vs baseline: 1.4889x; 1.0491x over previous
#include <cuda_runtime.h>

#define BB 4
#define NN 8192
#define PAIRS (NN / 2)
#define THREADS 256
#define UQ 4            // queries per thread
#define QBLOCKS 8       // worst-case coverage 8*1024 = 8192 queries
#define MSLICES 16
#define CHUNKP 512      // db pairs staged in smem (16KB)
#define FBLOCKS 64      // 64*256*4 = 65536 = 2*BB*NN, one float4/thread

// Scratch (device globals: no allocations allowed; BSS zero-init on first call,
// finalize's last block resets counters for subsequent graph replays)
__device__ float4 g_q [2][BB][NN];         // query points (x,y,z,|.|^2)
__device__ float  g_db2[2][BB][PAIRS][8];  // pair-interleaved db: [x0x1][y0y1][z0z1][w0w1]
__device__ float  g_minbuf[2][BB][NN];     // per-query clamped min (qw+e, >=0)
__device__ int    g_nv[BB];
__device__ float  g_l1sum;
__device__ float  g_cd;
__device__ int    g_ticket;

__device__ __forceinline__ unsigned long long pack2(float v) {
    unsigned long long r;
    asm("mov.b64 %0, {%1, %1};" : "=l"(r) : "f"(v));
    return r;
}

__device__ __forceinline__ unsigned long long fma2(unsigned long long a,
                                                   unsigned long long b,
                                                   unsigned long long c) {
    unsigned long long d;
    asm("fma.rn.f32x2 %0, %1, %2, %3;" : "=l"(d) : "l"(a), "l"(b), "l"(c));
    return d;
}

__global__ void prep_kernel(const float* __restrict__ pred,
                            const float* __restrict__ target,
                            const int*   __restrict__ mask,
                            const float* __restrict__ points) {
    int gid = blockIdx.x * blockDim.x + threadIdx.x;   // grid exactly covers BB*NN
    // init minbuf to +inf (index-based, no interaction with slot atomics)
    ((float*)g_minbuf)[gid]                = __int_as_float(0x7F800000);
    ((float*)g_minbuf)[gid + BB * NN]      = __int_as_float(0x7F800000);

    int b = gid / NN;
    int base = gid * 3;
    float p0 = pred[base], p1 = pred[base + 1], p2 = pred[base + 2];
    float t0 = target[base], t1 = target[base + 1], t2 = target[base + 2];
    int m = mask[gid];
    float li = 0.0f;
    if (m) {
        li = (fabsf(p0 - t0) + fabsf(p1 - t1) + fabsf(p2 - t2)) * (1.0f / 3.0f);
        float x0 = points[base], x1 = points[base + 1], x2 = points[base + 2];
        float c0 = x0 + t0, c1 = x1 + t1, c2 = x2 + t2;     // clean
        float q0 = x0 + p0, q1 = x1 + p1, q2 = x2 + p2;     // predp
        float cn = fmaf(c0, c0, fmaf(c1, c1, c2 * c2));
        float pn = fmaf(q0, q0, fmaf(q1, q1, q2 * q2));
        int slot = atomicAdd(&g_nv[b], 1);
        g_q[0][b][slot] = make_float4(c0, c1, c2, cn);
        g_q[1][b][slot] = make_float4(q0, q1, q2, pn);
        int pi = slot >> 1, h = slot & 1;
        // dir 0: queries=clean, db=pred points (store -2*p, |p|^2)
        float* d0 = &g_db2[0][b][pi][0];
        d0[0 + h] = -2.0f * q0; d0[2 + h] = -2.0f * q1;
        d0[4 + h] = -2.0f * q2; d0[6 + h] = pn;
        // dir 1: queries=pred, db=clean points
        float* d1 = &g_db2[1][b][pi][0];
        d1[0 + h] = -2.0f * c0; d1[2 + h] = -2.0f * c1;
        d1[4 + h] = -2.0f * c2; d1[6 + h] = cn;
    }
    #pragma unroll
    for (int o = 16; o; o >>= 1) li += __shfl_down_sync(0xFFFFFFFFu, li, o);
    if ((threadIdx.x & 31) == 0) atomicAdd(&g_l1sum, li);
}

__global__ void __launch_bounds__(THREADS)
pair_kernel() {
    int z = blockIdx.z;
    int dir = z & 1;
    int b = z >> 1;
    int nv = g_nv[b];
    int qbase = blockIdx.x * (THREADS * UQ);
    if (qbase >= nv) return;                          // block-uniform
    int nvp = (nv + 1) >> 1;                          // padded pair count
    int len = (nvp + MSLICES - 1) / MSLICES;
    int m0 = blockIdx.y * len;
    int m1 = min(m0 + len, nvp);
    if (m0 >= m1) return;                             // block-uniform
    bool oddnv = (nv & 1) != 0;
    int padidx = 2 * (nvp - 1) + 1;                   // float4 index of (z0,z1,w0,w1) of last pair

    __shared__ float4 sdb[2 * CHUNKP];

    const float4* __restrict__ Q  = g_q[dir][b];
    const float4* __restrict__ DB = (const float4*)&g_db2[dir][b][0][0];

    unsigned long long qx2[UQ], qy2[UQ], qz2[UQ];
    float qw[UQ], mnl[UQ], mnh[UQ];
    #pragma unroll
    for (int u = 0; u < UQ; u++) {
        int qi = min(qbase + u * THREADS + (int)threadIdx.x, nv - 1);
        float4 q = Q[qi];
        qx2[u] = pack2(q.x); qy2[u] = pack2(q.y); qz2[u] = pack2(q.z);
        qw[u] = q.w;
        mnl[u] = 3.4e38f; mnh[u] = 3.4e38f;
    }

    for (int mc = m0; mc < m1; mc += CHUNKP) {
        int cnt = min(CHUNKP, m1 - mc);
        __syncthreads();
        for (int t = threadIdx.x; t < cnt * 2; t += THREADS) {
            float4 v = DB[2 * mc + t];
            // patch the pad half of the last pair when nv is odd (stale slot)
            if (oddnv && (2 * mc + t) == padidx) v.w = 1e30f;
            sdb[t] = v;
        }
        __syncthreads();
        #pragma unroll 2
        for (int j = 0; j < cnt; j++) {
            ulonglong2 xy = *(const ulonglong2*)(sdb + 2 * j);      // x0x1 | y0y1
            ulonglong2 zw = *(const ulonglong2*)(sdb + 2 * j + 1);  // z0z1 | w0w1
            #pragma unroll
            for (int u = 0; u < UQ; u++) {
                // e2 = {w + (-2p).q} for both db halves at once
                unsigned long long acc = fma2(zw.x, qz2[u], zw.y);
                acc = fma2(xy.y, qy2[u], acc);
                acc = fma2(xy.x, qx2[u], acc);
                float elo, ehi;
                asm("mov.b64 {%0, %1}, %2;" : "=f"(elo), "=f"(ehi) : "l"(acc));
                mnl[u] = fminf(mnl[u], elo);
                mnh[u] = fminf(mnh[u], ehi);
            }
        }
    }

    #pragma unroll
    for (int u = 0; u < UQ; u++) {
        int qi = qbase + u * THREADS + (int)threadIdx.x;
        if (qi < nv) {
            // fold query norm + clamp (both monotone, commute past cross-block min)
            float val = fmaxf(qw[u] + fminf(mnl[u], mnh[u]), 0.0f);
            atomicMin((int*)&g_minbuf[dir][b][qi], __float_as_int(val)); // val >= 0
        }
    }
}

__global__ void __launch_bounds__(256)
finalize_kernel(float* __restrict__ out) {
    __shared__ float red[8];
    int tid = threadIdx.x;
    int idx4 = (blockIdx.x * 256 + tid) * 4;          // FBLOCKS*256*4 == 2*BB*NN exactly
    int b = (idx4 >> 13) & (BB - 1);
    int i = idx4 & (NN - 1);
    int nv = g_nv[b];
    float inv_nv = (nv > 0) ? (1.0f / (float)nv) : 0.0f;

    float4 v = *(const float4*)(((const float*)g_minbuf) + idx4);
    float s = 0.0f;
    if (i + 0 < nv) s += v.x;
    if (i + 1 < nv) s += v.y;
    if (i + 2 < nv) s += v.z;
    if (i + 3 < nv) s += v.w;
    float acc = s * inv_nv;

    #pragma unroll
    for (int o = 16; o; o >>= 1) acc += __shfl_down_sync(0xFFFFFFFFu, acc, o);
    if ((tid & 31) == 0) red[tid >> 5] = acc;
    __syncthreads();
    if (tid == 0) {
        float bs = red[0] + red[1] + red[2] + red[3] + red[4] + red[5] + red[6] + red[7];
        atomicAdd(&g_cd, bs);
        __threadfence();
        int ticket = atomicAdd(&g_ticket, 1);
        if (ticket == FBLOCKS - 1) {
            int cnt = g_nv[0] + g_nv[1] + g_nv[2] + g_nv[3];
            float l1 = *((volatile float*)&g_l1sum) / (float)max(cnt, 1);
            float cd = *((volatile float*)&g_cd) / (float)BB;
            out[0] = 0.5f * (l1 + cd);
            // reset for next graph replay (self-restoring launch)
            g_nv[0] = 0; g_nv[1] = 0; g_nv[2] = 0; g_nv[3] = 0;
            g_l1sum = 0.0f; g_cd = 0.0f; g_ticket = 0;
        }
    }
}

extern "C" void kernel_launch(void* const* d_in, const int* in_sizes, int n_in,
                              void* d_out, int out_size) {
    const float* pred   = (const float*)d_in[0];
    const float* target = (const float*)d_in[1];
    const int*   mask   = (const int*)d_in[2];
    const float* points = (const float*)d_in[3];

    prep_kernel<<<(BB * NN) / 256, 256>>>(pred, target, mask, points);
    pair_kernel<<<dim3(QBLOCKS, MSLICES, 2 * BB), THREADS>>>();
    finalize_kernel<<<FBLOCKS, 256>>>((float*)d_out);
}

// round 9
// speedup vs baseline: 1.6992x; 1.1412x over previous
#include <cuda_runtime.h>

#define BB 4
#define NN 8192
#define PAIRS (NN / 2)
#define THREADS 256
#define UQ 4            // queries per thread
#define QBLOCKS 8       // worst-case coverage 8*1024 = 8192 queries
#define MSLICES 16
#define CHUNKP 512      // db pairs staged in smem (16KB)
#define FBLOCKS 64      // 64*256*4 = 65536 = 2*BB*NN, one float4/thread
#define PREP_THREADS 64
#define PREP_BLOCKS (BB * NN / 4 / PREP_THREADS)   // 8192 threads, 4 pts each

// Scratch (device globals: no allocations allowed; BSS zero-init on first call,
// finalize's last block resets counters for subsequent graph replays)
__device__ float4 g_q [2][BB][NN];         // query points (x,y,z,|.|^2)
__device__ float  g_db2[2][BB][PAIRS][8];  // pair-interleaved db: [x0x1][y0y1][z0z1][w0w1]
__device__ float  g_minbuf[2][BB][NN];     // per-query clamped min (qw+e, >=0)
__device__ int    g_nv[BB];
__device__ float  g_l1sum;
__device__ float  g_cd;
__device__ int    g_ticket;

__device__ __forceinline__ unsigned long long pack2(float v) {
    unsigned long long r;
    asm("mov.b64 %0, {%1, %1};" : "=l"(r) : "f"(v));
    return r;
}

__device__ __forceinline__ unsigned long long fma2(unsigned long long a,
                                                   unsigned long long b,
                                                   unsigned long long c) {
    unsigned long long d;
    asm("fma.rn.f32x2 %0, %1, %2, %3;" : "=l"(d) : "l"(a), "l"(b), "l"(c));
    return d;
}

__global__ void __launch_bounds__(PREP_THREADS)
prep_kernel(const float* __restrict__ pred,
            const float* __restrict__ target,
            const int*   __restrict__ mask,
            const float* __restrict__ points) {
    int gid = blockIdx.x * PREP_THREADS + threadIdx.x;   // 0..8191, 4 points each

    // init minbuf to +inf (index-based, no interaction with slot atomics)
    float4 inf4 = make_float4(__int_as_float(0x7F800000), __int_as_float(0x7F800000),
                              __int_as_float(0x7F800000), __int_as_float(0x7F800000));
    ((float4*)g_minbuf)[gid * 2 + 0] = inf4;
    ((float4*)g_minbuf)[gid * 2 + 1] = inf4;

    int b = gid >> 11;                                   // 2048 threads per batch

    // wide loads: 4 points = 12 floats = 3 float4 from each tensor
    const float4* P4 = (const float4*)(pred   + (size_t)gid * 12);
    const float4* T4 = (const float4*)(target + (size_t)gid * 12);
    const float4* X4 = (const float4*)(points + (size_t)gid * 12);
    float4 pA = P4[0], pB = P4[1], pC = P4[2];
    float4 tA = T4[0], tB = T4[1], tC = T4[2];
    float4 xA = X4[0], xB = X4[1], xC = X4[2];
    int4 mm = *(const int4*)(mask + (size_t)gid * 4);

    float px[4] = {pA.x, pA.w, pB.z, pC.y};
    float py[4] = {pA.y, pB.x, pB.w, pC.z};
    float pz[4] = {pA.z, pB.y, pC.x, pC.w};
    float tx[4] = {tA.x, tA.w, tB.z, tC.y};
    float ty[4] = {tA.y, tB.x, tB.w, tC.z};
    float tz[4] = {tA.z, tB.y, tC.x, tC.w};
    float xx[4] = {xA.x, xA.w, xB.z, xC.y};
    float xy[4] = {xA.y, xB.x, xB.w, xC.z};
    float xz[4] = {xA.z, xB.y, xC.x, xC.w};
    int   mk[4] = {mm.x, mm.y, mm.z, mm.w};

    int cnt = mk[0] + mk[1] + mk[2] + mk[3];
    int slot = (cnt > 0) ? atomicAdd(&g_nv[b], cnt) : 0;

    float li = 0.0f;
    #pragma unroll
    for (int k = 0; k < 4; k++) {
        if (mk[k]) {
            li += (fabsf(px[k] - tx[k]) + fabsf(py[k] - ty[k]) + fabsf(pz[k] - tz[k]))
                  * (1.0f / 3.0f);
            float c0 = xx[k] + tx[k], c1 = xy[k] + ty[k], c2 = xz[k] + tz[k];   // clean
            float q0 = xx[k] + px[k], q1 = xy[k] + py[k], q2 = xz[k] + pz[k];   // predp
            float cn = fmaf(c0, c0, fmaf(c1, c1, c2 * c2));
            float pn = fmaf(q0, q0, fmaf(q1, q1, q2 * q2));
            g_q[0][b][slot] = make_float4(c0, c1, c2, cn);
            g_q[1][b][slot] = make_float4(q0, q1, q2, pn);
            int pi = slot >> 1, h = slot & 1;
            // dir 0: queries=clean, db=pred points (store -2*p, |p|^2)
            float* d0 = &g_db2[0][b][pi][0];
            d0[0 + h] = -2.0f * q0; d0[2 + h] = -2.0f * q1;
            d0[4 + h] = -2.0f * q2; d0[6 + h] = pn;
            // dir 1: queries=pred, db=clean points
            float* d1 = &g_db2[1][b][pi][0];
            d1[0 + h] = -2.0f * c0; d1[2 + h] = -2.0f * c1;
            d1[4 + h] = -2.0f * c2; d1[6 + h] = cn;
            slot++;
        }
    }

    #pragma unroll
    for (int o = 16; o; o >>= 1) li += __shfl_down_sync(0xFFFFFFFFu, li, o);
    if ((threadIdx.x & 31) == 0) atomicAdd(&g_l1sum, li);
}

__global__ void __launch_bounds__(THREADS)
pair_kernel() {
    int z = blockIdx.z;
    int dir = z & 1;
    int b = z >> 1;
    int nv = g_nv[b];
    int qbase = blockIdx.x * (THREADS * UQ);
    if (qbase >= nv) return;                          // block-uniform
    int nvp = (nv + 1) >> 1;                          // padded pair count
    int len = (nvp + MSLICES - 1) / MSLICES;
    int m0 = blockIdx.y * len;
    int m1 = min(m0 + len, nvp);
    if (m0 >= m1) return;                             // block-uniform
    bool oddnv = (nv & 1) != 0;
    int padidx = 2 * (nvp - 1) + 1;                   // float4 index of (z0,z1,w0,w1) of last pair

    __shared__ float4 sdb[2 * CHUNKP];

    const float4* __restrict__ Q  = g_q[dir][b];
    const float4* __restrict__ DB = (const float4*)&g_db2[dir][b][0][0];

    unsigned long long qx2[UQ], qy2[UQ], qz2[UQ];
    float qw[UQ], mnl[UQ], mnh[UQ];
    #pragma unroll
    for (int u = 0; u < UQ; u++) {
        int qi = min(qbase + u * THREADS + (int)threadIdx.x, nv - 1);
        float4 q = Q[qi];
        qx2[u] = pack2(q.x); qy2[u] = pack2(q.y); qz2[u] = pack2(q.z);
        qw[u] = q.w;
        mnl[u] = 3.4e38f; mnh[u] = 3.4e38f;
    }

    for (int mc = m0; mc < m1; mc += CHUNKP) {
        int cnt = min(CHUNKP, m1 - mc);
        __syncthreads();
        for (int t = threadIdx.x; t < cnt * 2; t += THREADS) {
            float4 v = DB[2 * mc + t];
            // patch the pad half of the last pair when nv is odd (stale slot)
            if (oddnv && (2 * mc + t) == padidx) v.w = 1e30f;
            sdb[t] = v;
        }
        __syncthreads();
        #pragma unroll 2
        for (int j = 0; j < cnt; j++) {
            ulonglong2 xy = *(const ulonglong2*)(sdb + 2 * j);      // x0x1 | y0y1
            ulonglong2 zw = *(const ulonglong2*)(sdb + 2 * j + 1);  // z0z1 | w0w1
            #pragma unroll
            for (int u = 0; u < UQ; u++) {
                // e2 = {w + (-2p).q} for both db halves at once
                unsigned long long acc = fma2(zw.x, qz2[u], zw.y);
                acc = fma2(xy.y, qy2[u], acc);
                acc = fma2(xy.x, qx2[u], acc);
                float elo, ehi;
                asm("mov.b64 {%0, %1}, %2;" : "=f"(elo), "=f"(ehi) : "l"(acc));
                mnl[u] = fminf(mnl[u], elo);
                mnh[u] = fminf(mnh[u], ehi);
            }
        }
    }

    #pragma unroll
    for (int u = 0; u < UQ; u++) {
        int qi = qbase + u * THREADS + (int)threadIdx.x;
        if (qi < nv) {
            // fold query norm + clamp (both monotone, commute past cross-block min)
            float val = fmaxf(qw[u] + fminf(mnl[u], mnh[u]), 0.0f);
            atomicMin((int*)&g_minbuf[dir][b][qi], __float_as_int(val)); // val >= 0
        }
    }
}

__global__ void __launch_bounds__(256)
finalize_kernel(float* __restrict__ out) {
    __shared__ float red[8];
    int tid = threadIdx.x;
    int idx4 = (blockIdx.x * 256 + tid) * 4;          // FBLOCKS*256*4 == 2*BB*NN exactly
    int b = (idx4 >> 13) & (BB - 1);
    int i = idx4 & (NN - 1);
    int nv = g_nv[b];
    float inv_nv = (nv > 0) ? (1.0f / (float)nv) : 0.0f;

    float4 v = *(const float4*)(((const float*)g_minbuf) + idx4);
    float s = 0.0f;
    if (i + 0 < nv) s += v.x;
    if (i + 1 < nv) s += v.y;
    if (i + 2 < nv) s += v.z;
    if (i + 3 < nv) s += v.w;
    float acc = s * inv_nv;

    #pragma unroll
    for (int o = 16; o; o >>= 1) acc += __shfl_down_sync(0xFFFFFFFFu, acc, o);
    if ((tid & 31) == 0) red[tid >> 5] = acc;
    __syncthreads();
    if (tid == 0) {
        float bs = red[0] + red[1] + red[2] + red[3] + red[4] + red[5] + red[6] + red[7];
        atomicAdd(&g_cd, bs);
        __threadfence();
        int ticket = atomicAdd(&g_ticket, 1);
        if (ticket == FBLOCKS - 1) {
            int cnt = g_nv[0] + g_nv[1] + g_nv[2] + g_nv[3];
            float l1 = *((volatile float*)&g_l1sum) / (float)max(cnt, 1);
            float cd = *((volatile float*)&g_cd) / (float)BB;
            out[0] = 0.5f * (l1 + cd);
            // reset for next graph replay (self-restoring launch)
            g_nv[0] = 0; g_nv[1] = 0; g_nv[2] = 0; g_nv[3] = 0;
            g_l1sum = 0.0f; g_cd = 0.0f; g_ticket = 0;
        }
    }
}

extern "C" void kernel_launch(void* const* d_in, const int* in_sizes, int n_in,
                              void* d_out, int out_size) {
    const float* pred   = (const float*)d_in[0];
    const float* target = (const float*)d_in[1];
    const int*   mask   = (const int*)d_in[2];
    const float* points = (const float*)d_in[3];

    prep_kernel<<<PREP_BLOCKS, PREP_THREADS>>>(pred, target, mask, points);
    pair_kernel<<<dim3(QBLOCKS, MSLICES, 2 * BB), THREADS>>>();
    finalize_kernel<<<FBLOCKS, 256>>>((float*)d_out);
}